// round 1
// baseline (speedup 1.0000x reference)
#include <cuda_runtime.h>
#include <math.h>

// Problem constants
#define B_  256
#define T_  200
#define E_  584
#define H_  8
#define HS_ 73
#define BH_ (B_*H_)      // 2048
#define M_  (B_*T_)      // 51200
#define KP_ 77           // padded head-size pitch in smem (gcd(77,32)=... 77%32=13, conflict-free)

// Scratch (allocation-free rule: __device__ globals)
__device__ float g_q[BH_*T_*HS_];
__device__ float g_k[BH_*T_*HS_];
__device__ float g_v[BH_*T_*HS_];
__device__ float g_att[M_*E_];

// ---------------------------------------------------------------------------
// GEMM 1: QKV projection.  C[m,n] = sum_k x[m,k] * W[n,k],  n in [0,1752)
// 128x128 tile, BK=8, 256 threads, 8x8 microtile.
// ---------------------------------------------------------------------------
__global__ __launch_bounds__(256, 2)
void qkv_gemm(const float* __restrict__ x,
              const float* __restrict__ Wq,
              const float* __restrict__ Wk,
              const float* __restrict__ Wv)
{
    __shared__ float As[8][132];
    __shared__ float Bs[8][132];

    const int tid = threadIdx.x;
    const int m0  = blockIdx.y * 128;
    const int n0  = blockIdx.x * 128;
    const int tx  = tid & 15;       // 0..15 -> col group
    const int ty  = tid >> 4;       // 0..15 -> row group

    float acc[8][8];
#pragma unroll
    for (int i = 0; i < 8; i++)
#pragma unroll
        for (int j = 0; j < 8; j++) acc[i][j] = 0.f;

    // staging indices: each thread loads one float4 of A and one of B per k-tile
    const int lm = tid >> 1;            // 0..127 (tile row)
    const int lk = (tid & 1) * 4;       // 0 or 4

    const float* Aptr = x + (size_t)(m0 + lm) * E_ + lk;

    const int   gn     = n0 + lm;
    const bool  bvalid = (gn < 3 * E_);
    int sel = gn / E_; if (sel > 2) sel = 2;
    int ln  = bvalid ? (gn - sel * E_) : 0;
    const float* Wsel = (sel == 0) ? Wq : ((sel == 1) ? Wk : Wv);
    const float* Bptr = Wsel + (size_t)ln * E_ + lk;

    for (int k0 = 0; k0 < E_; k0 += 8) {
        float4 av = *(const float4*)(Aptr + k0);
        float4 bv = bvalid ? *(const float4*)(Bptr + k0) : make_float4(0.f,0.f,0.f,0.f);

        __syncthreads();
        As[lk+0][lm] = av.x; As[lk+1][lm] = av.y; As[lk+2][lm] = av.z; As[lk+3][lm] = av.w;
        Bs[lk+0][lm] = bv.x; Bs[lk+1][lm] = bv.y; Bs[lk+2][lm] = bv.z; Bs[lk+3][lm] = bv.w;
        __syncthreads();

#pragma unroll
        for (int k = 0; k < 8; k++) {
            float a[8], b[8];
            *(float4*)&a[0] = *(const float4*)&As[k][ty*8];
            *(float4*)&a[4] = *(const float4*)&As[k][ty*8+4];
            *(float4*)&b[0] = *(const float4*)&Bs[k][tx*8];
            *(float4*)&b[4] = *(const float4*)&Bs[k][tx*8+4];
#pragma unroll
            for (int i = 0; i < 8; i++)
#pragma unroll
                for (int j = 0; j < 8; j++)
                    acc[i][j] = fmaf(a[i], b[j], acc[i][j]);
        }
    }

    // epilogue: scatter into g_q / g_k / g_v laid out [B, H, T, HS]
#pragma unroll
    for (int i = 0; i < 8; i++) {
        const int m  = m0 + ty*8 + i;
        const int bb = m / T_;
        const int t  = m - bb * T_;
#pragma unroll
        for (int j = 0; j < 8; j++) {
            const int n = n0 + tx*8 + j;
            if (n < 3 * E_) {
                const int s  = n / E_;
                const int l  = n - s * E_;
                const int hh = l / HS_;
                const int f  = l - hh * HS_;
                float* dst = (s == 0) ? g_q : ((s == 1) ? g_k : g_v);
                dst[((size_t)(bb*H_ + hh)*T_ + t)*HS_ + f] = acc[i][j];
            }
        }
    }
}

// ---------------------------------------------------------------------------
// Attention: one CTA per (b,h). K,V resident in smem; Q processed in 64-row
// tiles; warp-per-8-rows register softmax.
// ---------------------------------------------------------------------------
__global__ __launch_bounds__(256, 1)
void attn_kernel()
{
    extern __shared__ float sm[];
    float* Ks = sm;                    // [T_][KP_]
    float* Vs = Ks + T_ * KP_;         // [T_][KP_]
    float* Qs = Vs + T_ * KP_;         // [64][KP_]
    float* Ss = Qs + 64 * KP_;         // [64][T_]

    const int bh  = blockIdx.x;
    const int tid = threadIdx.x;
    const int tx  = tid & 31;
    const int wy  = tid >> 5;          // warp id 0..7 -> owns rows wy*8..wy*8+7
    const int b   = bh / H_;
    const int h   = bh - b * H_;

    const float* kg = g_k + (size_t)bh * T_ * HS_;
    const float* vg = g_v + (size_t)bh * T_ * HS_;
    const float* qg = g_q + (size_t)bh * T_ * HS_;

    for (int i = tid; i < T_ * HS_; i += 256) {
        const int s = i / HS_;
        const int f = i - s * HS_;
        Ks[s*KP_ + f] = kg[i];
        Vs[s*KP_ + f] = vg[i];
    }
    __syncthreads();

    const float scale = rsqrtf((float)E_);

    for (int t0 = 0; t0 < T_; t0 += 64) {
        const int rt = (T_ - t0 < 64) ? (T_ - t0) : 64;

        // load Q tile (zero-fill invalid rows)
        for (int i = tid; i < 64 * HS_; i += 256) {
            const int r = i / HS_;
            const int f = i - r * HS_;
            Qs[r*KP_ + f] = (r < rt) ? qg[(size_t)(t0 + r)*HS_ + f] : 0.f;
        }
        __syncthreads();

        // ---- scores: S[r][c] = Q[r] . K[c], rows wy*8..+7, cols tx+32j ----
        float pacc[8][7];
#pragma unroll
        for (int i = 0; i < 8; i++)
#pragma unroll
            for (int j = 0; j < 7; j++) pacc[i][j] = 0.f;

        int cidx[7];
#pragma unroll
        for (int j = 0; j < 7; j++) {
            int c = tx + 32*j;
            cidx[j] = (c < T_) ? c : (T_ - 1);
        }

        for (int f = 0; f < HS_; f++) {
            float kv[7];
#pragma unroll
            for (int j = 0; j < 7; j++) kv[j] = Ks[cidx[j]*KP_ + f];
#pragma unroll
            for (int i = 0; i < 8; i++) {
                const float qv = Qs[(wy*8 + i)*KP_ + f];
#pragma unroll
                for (int j = 0; j < 7; j++)
                    pacc[i][j] = fmaf(qv, kv[j], pacc[i][j]);
            }
        }

        // ---- masked softmax per row (warp-level), write normalized P to Ss ----
#pragma unroll
        for (int i = 0; i < 8; i++) {
            const int tg = t0 + wy*8 + i;   // global query index
            float sv[7];
            float mmax = -1e30f;
#pragma unroll
            for (int j = 0; j < 7; j++) {
                const int c = tx + 32*j;
                const bool ok = (c <= tg) && (c < T_) && (tg < T_);
                sv[j] = ok ? pacc[i][j] * scale : -1e30f;
                mmax = fmaxf(mmax, sv[j]);
            }
#pragma unroll
            for (int off = 16; off > 0; off >>= 1)
                mmax = fmaxf(mmax, __shfl_xor_sync(0xffffffffu, mmax, off));

            float sum = 0.f;
#pragma unroll
            for (int j = 0; j < 7; j++) {
                const float e = (sv[j] > -1e29f) ? __expf(sv[j] - mmax) : 0.f;
                sv[j] = e;
                sum += e;
            }
#pragma unroll
            for (int off = 16; off > 0; off >>= 1)
                sum += __shfl_xor_sync(0xffffffffu, sum, off);

            const float r = (sum > 0.f) ? (1.f / sum) : 0.f;
#pragma unroll
            for (int j = 0; j < 7; j++) {
                const int c = tx + 32*j;
                if (c < T_) Ss[(wy*8 + i)*T_ + c] = sv[j] * r;
            }
        }
        __syncthreads();

        // ---- O[r][f] = sum_s P[r][s] * V[s][f] ----
        float o0[8], o1[8], o2[8];
#pragma unroll
        for (int i = 0; i < 8; i++) { o0[i] = 0.f; o1[i] = 0.f; o2[i] = 0.f; }

        const int smax = (t0 + rt < T_) ? (t0 + rt) : T_;
        const bool f2ok = (tx + 64 < HS_);   // tx <= 8
        for (int s = 0; s < smax; s++) {
            const float v0 = Vs[s*KP_ + tx];
            const float v1 = Vs[s*KP_ + tx + 32];
            const float v2 = f2ok ? Vs[s*KP_ + tx + 64] : 0.f;
#pragma unroll
            for (int i = 0; i < 8; i++) {
                const float pv = Ss[(wy*8 + i)*T_ + s];
                o0[i] = fmaf(pv, v0, o0[i]);
                o1[i] = fmaf(pv, v1, o1[i]);
                o2[i] = fmaf(pv, v2, o2[i]);
            }
        }

        // store: g_att[(b*T + t)*E + h*HS + f]
#pragma unroll
        for (int i = 0; i < 8; i++) {
            const int tg = t0 + wy*8 + i;
            if (tg < T_) {
                float* dst = g_att + ((size_t)(b*T_ + tg))*E_ + h*HS_;
                dst[tx]      = o0[i];
                dst[tx + 32] = o1[i];
                if (f2ok) dst[tx + 64] = o2[i];
            }
        }
        __syncthreads();   // protect Qs/Ss before next tile
    }
}

// ---------------------------------------------------------------------------
// GEMM 2: output projection.  Y[m,n] = sum_k att[m,k] * Wo[n,k] + bo[n]
// ---------------------------------------------------------------------------
__global__ __launch_bounds__(256, 2)
void out_gemm(const float* __restrict__ Wo,
              const float* __restrict__ bo,
              float* __restrict__ out)
{
    __shared__ float As[8][132];
    __shared__ float Bs[8][132];

    const int tid = threadIdx.x;
    const int m0  = blockIdx.y * 128;
    const int n0  = blockIdx.x * 128;
    const int tx  = tid & 15;
    const int ty  = tid >> 4;

    float acc[8][8];
#pragma unroll
    for (int i = 0; i < 8; i++)
#pragma unroll
        for (int j = 0; j < 8; j++) acc[i][j] = 0.f;

    const int lm = tid >> 1;
    const int lk = (tid & 1) * 4;

    const float* Aptr = g_att + (size_t)(m0 + lm) * E_ + lk;

    const int  gn     = n0 + lm;
    const bool bvalid = (gn < E_);
    const float* Bptr = Wo + (size_t)(bvalid ? gn : 0) * E_ + lk;

    for (int k0 = 0; k0 < E_; k0 += 8) {
        float4 av = *(const float4*)(Aptr + k0);
        float4 bv = bvalid ? *(const float4*)(Bptr + k0) : make_float4(0.f,0.f,0.f,0.f);

        __syncthreads();
        As[lk+0][lm] = av.x; As[lk+1][lm] = av.y; As[lk+2][lm] = av.z; As[lk+3][lm] = av.w;
        Bs[lk+0][lm] = bv.x; Bs[lk+1][lm] = bv.y; Bs[lk+2][lm] = bv.z; Bs[lk+3][lm] = bv.w;
        __syncthreads();

#pragma unroll
        for (int k = 0; k < 8; k++) {
            float a[8], b[8];
            *(float4*)&a[0] = *(const float4*)&As[k][ty*8];
            *(float4*)&a[4] = *(const float4*)&As[k][ty*8+4];
            *(float4*)&b[0] = *(const float4*)&Bs[k][tx*8];
            *(float4*)&b[4] = *(const float4*)&Bs[k][tx*8+4];
#pragma unroll
            for (int i = 0; i < 8; i++)
#pragma unroll
                for (int j = 0; j < 8; j++)
                    acc[i][j] = fmaf(a[i], b[j], acc[i][j]);
        }
    }

#pragma unroll
    for (int i = 0; i < 8; i++) {
        const int m = m0 + ty*8 + i;
#pragma unroll
        for (int j = 0; j < 8; j++) {
            const int n = n0 + tx*8 + j;
            if (n < E_)
                out[(size_t)m * E_ + n] = acc[i][j] + bo[n];
        }
    }
}

// ---------------------------------------------------------------------------
extern "C" void kernel_launch(void* const* d_in, const int* in_sizes, int n_in,
                              void* d_out, int out_size)
{
    const float* x  = (const float*)d_in[0];
    const float* Wq = (const float*)d_in[1];
    const float* Wk = (const float*)d_in[2];
    const float* Wv = (const float*)d_in[3];
    const float* Wo = (const float*)d_in[4];
    const float* bo = (const float*)d_in[5];
    float* out = (float*)d_out;

    const int att_smem = (T_*KP_*2 + 64*KP_ + 64*T_) * (int)sizeof(float);  // ~194 KB
    cudaFuncSetAttribute(attn_kernel, cudaFuncAttributeMaxDynamicSharedMemorySize, att_smem);

    // QKV projection: N = 1752 -> 14 tiles, M = 51200 -> 400 tiles
    qkv_gemm<<<dim3(14, 400), 256>>>(x, Wq, Wk, Wv);

    // attention: one CTA per (b,h)
    attn_kernel<<<BH_, 256, att_smem>>>();

    // output projection: N = 584 -> 5 tiles
    out_gemm<<<dim3(5, 400), 256>>>(Wo, bo, out);
}

// round 3
// speedup vs baseline: 1.6658x; 1.6658x over previous
#include <cuda_runtime.h>
#include <math.h>
#include <stdint.h>

// Problem constants
#define B_  256
#define T_  200
#define E_  584
#define H_  8
#define HS_ 73
#define BH_ (B_*H_)      // 2048
#define M_  (B_*T_)      // 51200
#define KP_ 77           // smem pitch for attention tiles

// Scratch (allocation-free rule: __device__ globals)
__device__ float g_q[BH_*T_*HS_];
__device__ float g_k[BH_*T_*HS_];
__device__ float g_v[BH_*T_*HS_];
__device__ float g_att[M_*E_];

__device__ __forceinline__ uint32_t f2tf32(float f) {
    uint32_t r;
    asm("cvt.rna.tf32.f32 %0, %1;" : "=r"(r) : "f"(f));
    return r;
}

__device__ __forceinline__ void mma_tf32(float c[4],
                                         const uint32_t a[4],
                                         const uint32_t b[2]) {
    asm volatile(
        "mma.sync.aligned.m16n8k8.row.col.f32.tf32.tf32.f32 "
        "{%0,%1,%2,%3}, {%4,%5,%6,%7}, {%8,%9}, {%0,%1,%2,%3};"
        : "+f"(c[0]), "+f"(c[1]), "+f"(c[2]), "+f"(c[3])
        : "r"(a[0]), "r"(a[1]), "r"(a[2]), "r"(a[3]),
          "r"(b[0]), "r"(b[1]));
}

// ---------------------------------------------------------------------------
// TF32 tensor-core GEMM:  C[m,n] = sum_k A[m,k] * B[n,k]
// CTA tile 128x128, BK=16, 256 threads (8 warps, 4x2), warp tile 32x64.
// MODE 0: qkv projection (A = x arg; scatter to g_q/g_k/g_v)
// MODE 1: output projection (A = g_att device symbol; bias add -> out)
// ---------------------------------------------------------------------------
#define PITCH 136
#define NSTG  37          // ceil(584/16)

template<int MODE>
__global__ __launch_bounds__(256)
void gemm_tf32(const float* __restrict__ Aarg,
               const float* __restrict__ B0,
               const float* __restrict__ B1,
               const float* __restrict__ B2,
               const float* __restrict__ bias,
               float* __restrict__ out)
{
    __shared__ uint32_t As[2][16*PITCH];
    __shared__ uint32_t Bs[2][16*PITCH];

    // Resolve A in DEVICE code (passing __device__ symbols from host is UB).
    const float* A = (MODE == 0) ? Aarg : (const float*)g_att;

    const int tid  = threadIdx.x;
    const int lane = tid & 31;
    const int w    = tid >> 5;
    const int g    = lane >> 2;        // groupID
    const int c    = lane & 3;         // threadID_in_group
    const int mbase = (w & 3) * 32;
    const int nbase = (w >> 2) * 64;

    const int m0 = blockIdx.y * 128;
    const int n0 = blockIdx.x * 128;

    float acc[2][8][4];
#pragma unroll
    for (int mi = 0; mi < 2; mi++)
#pragma unroll
        for (int ni = 0; ni < 8; ni++)
#pragma unroll
            for (int r = 0; r < 4; r++) acc[mi][ni][r] = 0.f;

    // ---- staging indices: thread loads 2 float4 of A and 2 of B per stage --
    const int r0  = (tid * 2) >> 2;          // tile row for i=0
    const int kc0 = (tid * 2) & 3;
    const int r1  = (tid * 2 + 1) >> 2;
    const int kc1 = (tid * 2 + 1) & 3;

    const float* aptr0 = A + (size_t)(m0 + r0) * E_ + kc0 * 4;
    const float* aptr1 = A + (size_t)(m0 + r1) * E_ + kc1 * 4;

    // B row resolution (row-major [N, K] weights)
    const float* bptr0; const float* bptr1;
    bool bval0, bval1;
    {
        int gn0 = n0 + r0, gn1 = n0 + r1;
        if (MODE == 0) {
            bval0 = gn0 < 3 * E_;  bval1 = gn1 < 3 * E_;
            int s0 = gn0 / E_; if (s0 > 2) s0 = 2;
            int s1 = gn1 / E_; if (s1 > 2) s1 = 2;
            int l0 = bval0 ? gn0 - s0 * E_ : 0;
            int l1 = bval1 ? gn1 - s1 * E_ : 0;
            const float* W0 = (s0 == 0) ? B0 : ((s0 == 1) ? B1 : B2);
            const float* W1 = (s1 == 0) ? B0 : ((s1 == 1) ? B1 : B2);
            bptr0 = W0 + (size_t)l0 * E_ + kc0 * 4;
            bptr1 = W1 + (size_t)l1 * E_ + kc1 * 4;
        } else {
            bval0 = gn0 < E_;  bval1 = gn1 < E_;
            bptr0 = B0 + (size_t)(bval0 ? gn0 : 0) * E_ + kc0 * 4;
            bptr1 = B0 + (size_t)(bval1 ? gn1 : 0) * E_ + kc1 * 4;
        }
    }

    // ---- prologue: load stage 0 directly into buffer 0 ---------------------
    {
        const float4 z = make_float4(0.f, 0.f, 0.f, 0.f);
        float4 a0 = *(const float4*)aptr0;
        float4 a1 = *(const float4*)aptr1;
        float4 b0 = bval0 ? *(const float4*)bptr0 : z;
        float4 b1 = bval1 ? *(const float4*)bptr1 : z;
        uint32_t* as = As[0];
        uint32_t* bs = Bs[0];
        as[(kc0*4+0)*PITCH + r0] = f2tf32(a0.x);
        as[(kc0*4+1)*PITCH + r0] = f2tf32(a0.y);
        as[(kc0*4+2)*PITCH + r0] = f2tf32(a0.z);
        as[(kc0*4+3)*PITCH + r0] = f2tf32(a0.w);
        as[(kc1*4+0)*PITCH + r1] = f2tf32(a1.x);
        as[(kc1*4+1)*PITCH + r1] = f2tf32(a1.y);
        as[(kc1*4+2)*PITCH + r1] = f2tf32(a1.z);
        as[(kc1*4+3)*PITCH + r1] = f2tf32(a1.w);
        bs[(kc0*4+0)*PITCH + r0] = f2tf32(b0.x);
        bs[(kc0*4+1)*PITCH + r0] = f2tf32(b0.y);
        bs[(kc0*4+2)*PITCH + r0] = f2tf32(b0.z);
        bs[(kc0*4+3)*PITCH + r0] = f2tf32(b0.w);
        bs[(kc1*4+0)*PITCH + r1] = f2tf32(b1.x);
        bs[(kc1*4+1)*PITCH + r1] = f2tf32(b1.y);
        bs[(kc1*4+2)*PITCH + r1] = f2tf32(b1.z);
        bs[(kc1*4+3)*PITCH + r1] = f2tf32(b1.w);
    }
    __syncthreads();

    for (int s = 0; s < NSTG; s++) {
        const int buf = s & 1;

        // ---- issue global loads for next stage -----------------------------
        float4 na0, na1, nb0, nb1;
        const bool more = (s + 1 < NSTG);
        if (more) {
            const int k0 = (s + 1) * 16;
            const float4 z = make_float4(0.f, 0.f, 0.f, 0.f);
            const bool kv0 = (k0 + kc0 * 4) < E_;
            const bool kv1 = (k0 + kc1 * 4) < E_;
            na0 = kv0 ? *(const float4*)(aptr0 + k0) : z;
            na1 = kv1 ? *(const float4*)(aptr1 + k0) : z;
            nb0 = (kv0 && bval0) ? *(const float4*)(bptr0 + k0) : z;
            nb1 = (kv1 && bval1) ? *(const float4*)(bptr1 + k0) : z;
        }

        // ---- compute on current buffer -------------------------------------
        const uint32_t* as = As[buf];
        const uint32_t* bs = Bs[buf];
#pragma unroll
        for (int ks = 0; ks < 16; ks += 8) {
            uint32_t af[2][4];
            uint32_t bf[8][2];
#pragma unroll
            for (int mi = 0; mi < 2; mi++) {
                const int mr = mbase + mi * 16 + g;
                af[mi][0] = as[(ks + c)     * PITCH + mr];
                af[mi][1] = as[(ks + c)     * PITCH + mr + 8];
                af[mi][2] = as[(ks + c + 4) * PITCH + mr];
                af[mi][3] = as[(ks + c + 4) * PITCH + mr + 8];
            }
#pragma unroll
            for (int ni = 0; ni < 8; ni++) {
                const int nr = nbase + ni * 8 + g;
                bf[ni][0] = bs[(ks + c)     * PITCH + nr];
                bf[ni][1] = bs[(ks + c + 4) * PITCH + nr];
            }
#pragma unroll
            for (int mi = 0; mi < 2; mi++)
#pragma unroll
                for (int ni = 0; ni < 8; ni++)
                    mma_tf32(acc[mi][ni], af[mi], bf[ni]);
        }

        // ---- store next stage into other buffer ----------------------------
        if (more) {
            uint32_t* asn = As[buf ^ 1];
            uint32_t* bsn = Bs[buf ^ 1];
            asn[(kc0*4+0)*PITCH + r0] = f2tf32(na0.x);
            asn[(kc0*4+1)*PITCH + r0] = f2tf32(na0.y);
            asn[(kc0*4+2)*PITCH + r0] = f2tf32(na0.z);
            asn[(kc0*4+3)*PITCH + r0] = f2tf32(na0.w);
            asn[(kc1*4+0)*PITCH + r1] = f2tf32(na1.x);
            asn[(kc1*4+1)*PITCH + r1] = f2tf32(na1.y);
            asn[(kc1*4+2)*PITCH + r1] = f2tf32(na1.z);
            asn[(kc1*4+3)*PITCH + r1] = f2tf32(na1.w);
            bsn[(kc0*4+0)*PITCH + r0] = f2tf32(nb0.x);
            bsn[(kc0*4+1)*PITCH + r0] = f2tf32(nb0.y);
            bsn[(kc0*4+2)*PITCH + r0] = f2tf32(nb0.z);
            bsn[(kc0*4+3)*PITCH + r0] = f2tf32(nb0.w);
            bsn[(kc1*4+0)*PITCH + r1] = f2tf32(nb1.x);
            bsn[(kc1*4+1)*PITCH + r1] = f2tf32(nb1.y);
            bsn[(kc1*4+2)*PITCH + r1] = f2tf32(nb1.z);
            bsn[(kc1*4+3)*PITCH + r1] = f2tf32(nb1.w);
        }
        __syncthreads();
    }

    // ---- epilogue -----------------------------------------------------------
#pragma unroll
    for (int mi = 0; mi < 2; mi++) {
#pragma unroll
        for (int ni = 0; ni < 8; ni++) {
#pragma unroll
            for (int r = 0; r < 4; r++) {
                const int m = m0 + mbase + mi * 16 + g + ((r >= 2) ? 8 : 0);
                const int n = n0 + nbase + ni * 8 + 2 * c + (r & 1);
                const float v = acc[mi][ni][r];
                if (MODE == 0) {
                    if (n < 3 * E_) {
                        const int sidx = n / E_;
                        const int l    = n - sidx * E_;
                        const int hh   = l / HS_;
                        const int f    = l - hh * HS_;
                        const int bb   = m / T_;
                        const int t    = m - bb * T_;
                        float* dst = (sidx == 0) ? g_q : ((sidx == 1) ? g_k : g_v);
                        dst[((size_t)(bb * H_ + hh) * T_ + t) * HS_ + f] = v;
                    }
                } else {
                    if (n < E_)
                        out[(size_t)m * E_ + n] = v + bias[n];
                }
            }
        }
    }
}

// ---------------------------------------------------------------------------
// Attention: one CTA per (b,h). K,V resident in smem; Q processed in 64-row
// tiles; warp-per-8-rows register softmax.
// ---------------------------------------------------------------------------
__global__ __launch_bounds__(256, 1)
void attn_kernel()
{
    extern __shared__ float sm[];
    float* Ks = sm;                    // [T_][KP_]
    float* Vs = Ks + T_ * KP_;         // [T_][KP_]
    float* Qs = Vs + T_ * KP_;         // [64][KP_]
    float* Ss = Qs + 64 * KP_;         // [64][T_]

    const int bh  = blockIdx.x;
    const int tid = threadIdx.x;
    const int tx  = tid & 31;
    const int wy  = tid >> 5;
    const int b   = bh / H_;
    const int h   = bh - b * H_;

    const float* kg = g_k + (size_t)bh * T_ * HS_;
    const float* vg = g_v + (size_t)bh * T_ * HS_;
    const float* qg = g_q + (size_t)bh * T_ * HS_;

    for (int i = tid; i < T_ * HS_; i += 256) {
        const int s = i / HS_;
        const int f = i - s * HS_;
        Ks[s*KP_ + f] = kg[i];
        Vs[s*KP_ + f] = vg[i];
    }
    __syncthreads();

    const float scale = rsqrtf((float)E_);

    for (int t0 = 0; t0 < T_; t0 += 64) {
        const int rt = (T_ - t0 < 64) ? (T_ - t0) : 64;

        for (int i = tid; i < 64 * HS_; i += 256) {
            const int r = i / HS_;
            const int f = i - r * HS_;
            Qs[r*KP_ + f] = (r < rt) ? qg[(size_t)(t0 + r)*HS_ + f] : 0.f;
        }
        __syncthreads();

        float pacc[8][7];
#pragma unroll
        for (int i = 0; i < 8; i++)
#pragma unroll
            for (int j = 0; j < 7; j++) pacc[i][j] = 0.f;

        int cidx[7];
#pragma unroll
        for (int j = 0; j < 7; j++) {
            int cc = tx + 32*j;
            cidx[j] = (cc < T_) ? cc : (T_ - 1);
        }

        for (int f = 0; f < HS_; f++) {
            float kv[7];
#pragma unroll
            for (int j = 0; j < 7; j++) kv[j] = Ks[cidx[j]*KP_ + f];
#pragma unroll
            for (int i = 0; i < 8; i++) {
                const float qv = Qs[(wy*8 + i)*KP_ + f];
#pragma unroll
                for (int j = 0; j < 7; j++)
                    pacc[i][j] = fmaf(qv, kv[j], pacc[i][j]);
            }
        }

#pragma unroll
        for (int i = 0; i < 8; i++) {
            const int tg = t0 + wy*8 + i;
            float sv[7];
            float mmax = -1e30f;
#pragma unroll
            for (int j = 0; j < 7; j++) {
                const int cc = tx + 32*j;
                const bool ok = (cc <= tg) && (cc < T_) && (tg < T_);
                sv[j] = ok ? pacc[i][j] * scale : -1e30f;
                mmax = fmaxf(mmax, sv[j]);
            }
#pragma unroll
            for (int off = 16; off > 0; off >>= 1)
                mmax = fmaxf(mmax, __shfl_xor_sync(0xffffffffu, mmax, off));

            float sum = 0.f;
#pragma unroll
            for (int j = 0; j < 7; j++) {
                const float e = (sv[j] > -1e29f) ? __expf(sv[j] - mmax) : 0.f;
                sv[j] = e;
                sum += e;
            }
#pragma unroll
            for (int off = 16; off > 0; off >>= 1)
                sum += __shfl_xor_sync(0xffffffffu, sum, off);

            const float r = (sum > 0.f) ? (1.f / sum) : 0.f;
#pragma unroll
            for (int j = 0; j < 7; j++) {
                const int cc = tx + 32*j;
                if (cc < T_) Ss[(wy*8 + i)*T_ + cc] = sv[j] * r;
            }
        }
        __syncthreads();

        float o0[8], o1[8], o2[8];
#pragma unroll
        for (int i = 0; i < 8; i++) { o0[i] = 0.f; o1[i] = 0.f; o2[i] = 0.f; }

        const int smax = (t0 + rt < T_) ? (t0 + rt) : T_;
        const bool f2ok = (tx + 64 < HS_);
        for (int s = 0; s < smax; s++) {
            const float v0 = Vs[s*KP_ + tx];
            const float v1 = Vs[s*KP_ + tx + 32];
            const float v2 = f2ok ? Vs[s*KP_ + tx + 64] : 0.f;
#pragma unroll
            for (int i = 0; i < 8; i++) {
                const float pv = Ss[(wy*8 + i)*T_ + s];
                o0[i] = fmaf(pv, v0, o0[i]);
                o1[i] = fmaf(pv, v1, o1[i]);
                o2[i] = fmaf(pv, v2, o2[i]);
            }
        }

#pragma unroll
        for (int i = 0; i < 8; i++) {
            const int tg = t0 + wy*8 + i;
            if (tg < T_) {
                float* dst = g_att + ((size_t)(b*T_ + tg))*E_ + h*HS_;
                dst[tx]      = o0[i];
                dst[tx + 32] = o1[i];
                if (f2ok) dst[tx + 64] = o2[i];
            }
        }
        __syncthreads();
    }
}

// ---------------------------------------------------------------------------
extern "C" void kernel_launch(void* const* d_in, const int* in_sizes, int n_in,
                              void* d_out, int out_size)
{
    const float* x  = (const float*)d_in[0];
    const float* Wq = (const float*)d_in[1];
    const float* Wk = (const float*)d_in[2];
    const float* Wv = (const float*)d_in[3];
    const float* Wo = (const float*)d_in[4];
    const float* bo = (const float*)d_in[5];
    float* out = (float*)d_out;

    const int att_smem = (T_*KP_*2 + 64*KP_ + 64*T_) * (int)sizeof(float);
    cudaFuncSetAttribute(attn_kernel, cudaFuncAttributeMaxDynamicSharedMemorySize, att_smem);

    // QKV projection: N = 1752 -> 14 tiles, M = 51200 -> 400 tiles
    gemm_tf32<0><<<dim3(14, 400), 256>>>(x, Wq, Wk, Wv, nullptr, nullptr);

    // attention: one CTA per (b,h)
    attn_kernel<<<BH_, 256, att_smem>>>();

    // output projection: N = 584 -> 5 tiles (A resolved to g_att in device code)
    gemm_tf32<1><<<dim3(5, 400), 256>>>(nullptr, Wo, nullptr, nullptr, bo, out);
}

// round 4
// speedup vs baseline: 2.0784x; 1.2477x over previous
#include <cuda_runtime.h>
#include <math.h>
#include <stdint.h>

// Problem constants
#define B_  256
#define T_  200
#define E_  584
#define H_  8
#define HS_ 73
#define BH_ (B_*H_)      // 2048
#define M_  (B_*T_)      // 51200

// Scratch (allocation-free rule: __device__ globals)
__device__ float g_q[BH_*T_*HS_];
__device__ float g_k[BH_*T_*HS_];
__device__ float g_v[BH_*T_*HS_];
__device__ float g_att[M_*E_];

__device__ __forceinline__ uint32_t f2tf32(float f) {
    uint32_t r;
    asm("cvt.rna.tf32.f32 %0, %1;" : "=r"(r) : "f"(f));
    return r;
}

__device__ __forceinline__ void mma_tf32(float c[4],
                                         uint32_t a0, uint32_t a1, uint32_t a2, uint32_t a3,
                                         uint32_t b0, uint32_t b1) {
    asm volatile(
        "mma.sync.aligned.m16n8k8.row.col.f32.tf32.tf32.f32 "
        "{%0,%1,%2,%3}, {%4,%5,%6,%7}, {%8,%9}, {%0,%1,%2,%3};"
        : "+f"(c[0]), "+f"(c[1]), "+f"(c[2]), "+f"(c[3])
        : "r"(a0), "r"(a1), "r"(a2), "r"(a3), "r"(b0), "r"(b1));
}

// ---------------------------------------------------------------------------
// TF32 tensor-core GEMM (unchanged from R3):  C[m,n] = sum_k A[m,k] * B[n,k]
// ---------------------------------------------------------------------------
#define PITCH 136
#define NSTG  37          // ceil(584/16)

template<int MODE>
__global__ __launch_bounds__(256)
void gemm_tf32(const float* __restrict__ Aarg,
               const float* __restrict__ B0,
               const float* __restrict__ B1,
               const float* __restrict__ B2,
               const float* __restrict__ bias,
               float* __restrict__ out)
{
    __shared__ uint32_t As[2][16*PITCH];
    __shared__ uint32_t Bs[2][16*PITCH];

    const float* A = (MODE == 0) ? Aarg : (const float*)g_att;

    const int tid  = threadIdx.x;
    const int lane = tid & 31;
    const int w    = tid >> 5;
    const int g    = lane >> 2;
    const int c    = lane & 3;
    const int mbase = (w & 3) * 32;
    const int nbase = (w >> 2) * 64;

    const int m0 = blockIdx.y * 128;
    const int n0 = blockIdx.x * 128;

    float acc[2][8][4];
#pragma unroll
    for (int mi = 0; mi < 2; mi++)
#pragma unroll
        for (int ni = 0; ni < 8; ni++)
#pragma unroll
            for (int r = 0; r < 4; r++) acc[mi][ni][r] = 0.f;

    const int r0  = (tid * 2) >> 2;
    const int kc0 = (tid * 2) & 3;
    const int r1  = (tid * 2 + 1) >> 2;
    const int kc1 = (tid * 2 + 1) & 3;

    const float* aptr0 = A + (size_t)(m0 + r0) * E_ + kc0 * 4;
    const float* aptr1 = A + (size_t)(m0 + r1) * E_ + kc1 * 4;

    const float* bptr0; const float* bptr1;
    bool bval0, bval1;
    {
        int gn0 = n0 + r0, gn1 = n0 + r1;
        if (MODE == 0) {
            bval0 = gn0 < 3 * E_;  bval1 = gn1 < 3 * E_;
            int s0 = gn0 / E_; if (s0 > 2) s0 = 2;
            int s1 = gn1 / E_; if (s1 > 2) s1 = 2;
            int l0 = bval0 ? gn0 - s0 * E_ : 0;
            int l1 = bval1 ? gn1 - s1 * E_ : 0;
            const float* W0 = (s0 == 0) ? B0 : ((s0 == 1) ? B1 : B2);
            const float* W1 = (s1 == 0) ? B0 : ((s1 == 1) ? B1 : B2);
            bptr0 = W0 + (size_t)l0 * E_ + kc0 * 4;
            bptr1 = W1 + (size_t)l1 * E_ + kc1 * 4;
        } else {
            bval0 = gn0 < E_;  bval1 = gn1 < E_;
            bptr0 = B0 + (size_t)(bval0 ? gn0 : 0) * E_ + kc0 * 4;
            bptr1 = B0 + (size_t)(bval1 ? gn1 : 0) * E_ + kc1 * 4;
        }
    }

    {
        const float4 z = make_float4(0.f, 0.f, 0.f, 0.f);
        float4 a0 = *(const float4*)aptr0;
        float4 a1 = *(const float4*)aptr1;
        float4 b0 = bval0 ? *(const float4*)bptr0 : z;
        float4 b1 = bval1 ? *(const float4*)bptr1 : z;
        uint32_t* as = As[0];
        uint32_t* bs = Bs[0];
        as[(kc0*4+0)*PITCH + r0] = f2tf32(a0.x);
        as[(kc0*4+1)*PITCH + r0] = f2tf32(a0.y);
        as[(kc0*4+2)*PITCH + r0] = f2tf32(a0.z);
        as[(kc0*4+3)*PITCH + r0] = f2tf32(a0.w);
        as[(kc1*4+0)*PITCH + r1] = f2tf32(a1.x);
        as[(kc1*4+1)*PITCH + r1] = f2tf32(a1.y);
        as[(kc1*4+2)*PITCH + r1] = f2tf32(a1.z);
        as[(kc1*4+3)*PITCH + r1] = f2tf32(a1.w);
        bs[(kc0*4+0)*PITCH + r0] = f2tf32(b0.x);
        bs[(kc0*4+1)*PITCH + r0] = f2tf32(b0.y);
        bs[(kc0*4+2)*PITCH + r0] = f2tf32(b0.z);
        bs[(kc0*4+3)*PITCH + r0] = f2tf32(b0.w);
        bs[(kc1*4+0)*PITCH + r1] = f2tf32(b1.x);
        bs[(kc1*4+1)*PITCH + r1] = f2tf32(b1.y);
        bs[(kc1*4+2)*PITCH + r1] = f2tf32(b1.z);
        bs[(kc1*4+3)*PITCH + r1] = f2tf32(b1.w);
    }
    __syncthreads();

    for (int s = 0; s < NSTG; s++) {
        const int buf = s & 1;

        float4 na0, na1, nb0, nb1;
        const bool more = (s + 1 < NSTG);
        if (more) {
            const int k0 = (s + 1) * 16;
            const float4 z = make_float4(0.f, 0.f, 0.f, 0.f);
            const bool kv0 = (k0 + kc0 * 4) < E_;
            const bool kv1 = (k0 + kc1 * 4) < E_;
            na0 = kv0 ? *(const float4*)(aptr0 + k0) : z;
            na1 = kv1 ? *(const float4*)(aptr1 + k0) : z;
            nb0 = (kv0 && bval0) ? *(const float4*)(bptr0 + k0) : z;
            nb1 = (kv1 && bval1) ? *(const float4*)(bptr1 + k0) : z;
        }

        const uint32_t* as = As[buf];
        const uint32_t* bs = Bs[buf];
#pragma unroll
        for (int ks = 0; ks < 16; ks += 8) {
            uint32_t af[2][4];
            uint32_t bf[8][2];
#pragma unroll
            for (int mi = 0; mi < 2; mi++) {
                const int mr = mbase + mi * 16 + g;
                af[mi][0] = as[(ks + c)     * PITCH + mr];
                af[mi][1] = as[(ks + c)     * PITCH + mr + 8];
                af[mi][2] = as[(ks + c + 4) * PITCH + mr];
                af[mi][3] = as[(ks + c + 4) * PITCH + mr + 8];
            }
#pragma unroll
            for (int ni = 0; ni < 8; ni++) {
                const int nr = nbase + ni * 8 + g;
                bf[ni][0] = bs[(ks + c)     * PITCH + nr];
                bf[ni][1] = bs[(ks + c + 4) * PITCH + nr];
            }
#pragma unroll
            for (int mi = 0; mi < 2; mi++)
#pragma unroll
                for (int ni = 0; ni < 8; ni++)
                    mma_tf32(acc[mi][ni], af[mi][0], af[mi][1], af[mi][2], af[mi][3],
                             bf[ni][0], bf[ni][1]);
        }

        if (more) {
            uint32_t* asn = As[buf ^ 1];
            uint32_t* bsn = Bs[buf ^ 1];
            asn[(kc0*4+0)*PITCH + r0] = f2tf32(na0.x);
            asn[(kc0*4+1)*PITCH + r0] = f2tf32(na0.y);
            asn[(kc0*4+2)*PITCH + r0] = f2tf32(na0.z);
            asn[(kc0*4+3)*PITCH + r0] = f2tf32(na0.w);
            asn[(kc1*4+0)*PITCH + r1] = f2tf32(na1.x);
            asn[(kc1*4+1)*PITCH + r1] = f2tf32(na1.y);
            asn[(kc1*4+2)*PITCH + r1] = f2tf32(na1.z);
            asn[(kc1*4+3)*PITCH + r1] = f2tf32(na1.w);
            bsn[(kc0*4+0)*PITCH + r0] = f2tf32(nb0.x);
            bsn[(kc0*4+1)*PITCH + r0] = f2tf32(nb0.y);
            bsn[(kc0*4+2)*PITCH + r0] = f2tf32(nb0.z);
            bsn[(kc0*4+3)*PITCH + r0] = f2tf32(nb0.w);
            bsn[(kc1*4+0)*PITCH + r1] = f2tf32(nb1.x);
            bsn[(kc1*4+1)*PITCH + r1] = f2tf32(nb1.y);
            bsn[(kc1*4+2)*PITCH + r1] = f2tf32(nb1.z);
            bsn[(kc1*4+3)*PITCH + r1] = f2tf32(nb1.w);
        }
        __syncthreads();
    }

#pragma unroll
    for (int mi = 0; mi < 2; mi++) {
#pragma unroll
        for (int ni = 0; ni < 8; ni++) {
#pragma unroll
            for (int r = 0; r < 4; r++) {
                const int m = m0 + mbase + mi * 16 + g + ((r >= 2) ? 8 : 0);
                const int n = n0 + nbase + ni * 8 + 2 * c + (r & 1);
                const float v = acc[mi][ni][r];
                if (MODE == 0) {
                    if (n < 3 * E_) {
                        const int sidx = n / E_;
                        const int l    = n - sidx * E_;
                        const int hh   = l / HS_;
                        const int f    = l - hh * HS_;
                        const int bb   = m / T_;
                        const int t    = m - bb * T_;
                        float* dst = (sidx == 0) ? g_q : ((sidx == 1) ? g_k : g_v);
                        dst[((size_t)(bb * H_ + hh) * T_ + t) * HS_ + f] = v;
                    }
                } else {
                    if (n < E_)
                        out[(size_t)m * E_ + n] = v + bias[n];
                }
            }
        }
    }
}

// ---------------------------------------------------------------------------
// Tensor-core attention. One CTA per (b,h), 8 warps.
// All tiles in natural row-major with pitches chosen mod-32 for conflict-free
// mma fragment reads:
//   Qs  [64][QP=84]   tf32, A-operand (m-major, pitch%32==20)
//   Ks  [208][KP2=84] tf32, B-operand n-major (pitch%32==20)
//   Vs  [208][VP=88]  tf32, B-operand k-major (pitch%32==24)
//   Pt  [64][PP=212]  tf32, A-operand (pitch%32==20)
// ---------------------------------------------------------------------------
#define TP2 208
#define FP2 80
#define QP  84
#define KQ2 84
#define VP  88
#define PP  212

__global__ __launch_bounds__(256, 1)
void attn_mma()
{
    extern __shared__ uint32_t smu[];
    uint32_t* Ks = smu;                     // [208][84]
    uint32_t* Vs = Ks + TP2*KQ2;            // [208][88]
    uint32_t* Qs = Vs + TP2*VP;             // [64][84]
    uint32_t* Pt = Qs + 64*QP;              // [64][212]
    float* pmax  = (float*)(Pt + 64*PP);    // [64][2]
    float* psum  = pmax + 128;              // [64][2]

    const int bh   = blockIdx.x;
    const int tid  = threadIdx.x;
    const int lane = tid & 31;
    const int w    = tid >> 5;
    const int g    = lane >> 2;
    const int c    = lane & 3;
    const int wm   = w & 3;        // m-warp 0..3 (16 rows each)
    const int wn   = w >> 2;       // n-warp 0..1
    const int b    = bh / H_;
    const int h    = bh - b * H_;

    const float* qg = g_q + (size_t)bh * T_ * HS_;
    const float* kg = g_k + (size_t)bh * T_ * HS_;
    const float* vg = g_v + (size_t)bh * T_ * HS_;

    // ---- load K, V as tf32 (zero-padded) --------------------------------
    for (int i = tid; i < TP2*KQ2; i += 256) {
        const int s = i / KQ2, f = i - s * KQ2;
        Ks[i] = (s < T_ && f < HS_) ? f2tf32(kg[s*HS_ + f]) : 0u;
    }
    for (int i = tid; i < TP2*VP; i += 256) {
        const int s = i / VP, f = i - s * VP;
        Vs[i] = (s < T_ && f < HS_) ? f2tf32(vg[s*HS_ + f]) : 0u;
    }

    const float scale = rsqrtf((float)E_);
    const int mr = wm * 16;

    for (int t0 = 0; t0 < T_; t0 += 64) {
        // ---- load Q tile -------------------------------------------------
        __syncthreads();
        for (int i = tid; i < 64*QP; i += 256) {
            const int r = i / QP, f = i - r * QP;
            const int tg = t0 + r;
            Qs[i] = (tg < T_ && f < HS_) ? f2tf32(qg[tg*HS_ + f]) : 0u;
        }
        __syncthreads();

        // ---- S = Q . K^T   (warp tile 16 x 104) --------------------------
        const int nb  = wn * 104;
        const int thi = t0 + mr + 15;   // highest t row this warp touches
        float acc[13][4];
#pragma unroll
        for (int ni = 0; ni < 13; ni++)
#pragma unroll
            for (int r = 0; r < 4; r++) acc[ni][r] = 0.f;

        for (int ks = 0; ks < FP2; ks += 8) {
            const uint32_t a0 = Qs[(mr+g)  *QP + ks+c];
            const uint32_t a1 = Qs[(mr+g+8)*QP + ks+c];
            const uint32_t a2 = Qs[(mr+g)  *QP + ks+c+4];
            const uint32_t a3 = Qs[(mr+g+8)*QP + ks+c+4];
#pragma unroll
            for (int ni = 0; ni < 13; ni++) {
                if (nb + ni*8 <= thi) {   // causal block skip (warp-uniform)
                    const uint32_t b0 = Ks[(nb+ni*8+g)*KQ2 + ks+c];
                    const uint32_t b1 = Ks[(nb+ni*8+g)*KQ2 + ks+c+4];
                    mma_tf32(acc[ni], a0, a1, a2, a3, b0, b1);
                }
            }
        }

        // ---- softmax (register + tiny smem cross-half exchange) ----------
        const int t_lo = t0 + mr + g;
        const int t_hi = t_lo + 8;

        float mlo = -1e30f, mhi = -1e30f;
#pragma unroll
        for (int ni = 0; ni < 13; ni++) {
            const int s0 = nb + ni*8 + 2*c;
            const int s1 = s0 + 1;
            const bool ok0l = (s0 <= t_lo) && (s0 < T_) && (t_lo < T_);
            const bool ok1l = (s1 <= t_lo) && (s1 < T_) && (t_lo < T_);
            const bool ok0h = (s0 <= t_hi) && (s0 < T_) && (t_hi < T_);
            const bool ok1h = (s1 <= t_hi) && (s1 < T_) && (t_hi < T_);
            if (ok0l) mlo = fmaxf(mlo, acc[ni][0]*scale);
            if (ok1l) mlo = fmaxf(mlo, acc[ni][1]*scale);
            if (ok0h) mhi = fmaxf(mhi, acc[ni][2]*scale);
            if (ok1h) mhi = fmaxf(mhi, acc[ni][3]*scale);
        }
#pragma unroll
        for (int off = 1; off <= 2; off <<= 1) {
            mlo = fmaxf(mlo, __shfl_xor_sync(0xffffffffu, mlo, off));
            mhi = fmaxf(mhi, __shfl_xor_sync(0xffffffffu, mhi, off));
        }
        if (c == 0) {
            pmax[(mr+g)  *2 + wn] = mlo;
            pmax[(mr+g+8)*2 + wn] = mhi;
        }
        __syncthreads();
        const float gmlo = fmaxf(pmax[(mr+g)*2],   pmax[(mr+g)*2+1]);
        const float gmhi = fmaxf(pmax[(mr+g+8)*2], pmax[(mr+g+8)*2+1]);

        float slo = 0.f, shi = 0.f;
#pragma unroll
        for (int ni = 0; ni < 13; ni++) {
            const int s0 = nb + ni*8 + 2*c;
            const int s1 = s0 + 1;
            const bool ok0l = (s0 <= t_lo) && (s0 < T_) && (t_lo < T_);
            const bool ok1l = (s1 <= t_lo) && (s1 < T_) && (t_lo < T_);
            const bool ok0h = (s0 <= t_hi) && (s0 < T_) && (t_hi < T_);
            const bool ok1h = (s1 <= t_hi) && (s1 < T_) && (t_hi < T_);
            float e0 = ok0l ? __expf(acc[ni][0]*scale - gmlo) : 0.f;
            float e1 = ok1l ? __expf(acc[ni][1]*scale - gmlo) : 0.f;
            float e2 = ok0h ? __expf(acc[ni][2]*scale - gmhi) : 0.f;
            float e3 = ok1h ? __expf(acc[ni][3]*scale - gmhi) : 0.f;
            acc[ni][0] = e0; acc[ni][1] = e1; acc[ni][2] = e2; acc[ni][3] = e3;
            slo += e0 + e1;  shi += e2 + e3;
        }
#pragma unroll
        for (int off = 1; off <= 2; off <<= 1) {
            slo += __shfl_xor_sync(0xffffffffu, slo, off);
            shi += __shfl_xor_sync(0xffffffffu, shi, off);
        }
        if (c == 0) {
            psum[(mr+g)  *2 + wn] = slo;
            psum[(mr+g+8)*2 + wn] = shi;
        }
        __syncthreads();
        const float tlo = psum[(mr+g)*2]   + psum[(mr+g)*2+1];
        const float thi2 = psum[(mr+g+8)*2] + psum[(mr+g+8)*2+1];
        const float rlo = (tlo  > 0.f) ? (1.f / tlo)  : 0.f;
        const float rhi = (thi2 > 0.f) ? (1.f / thi2) : 0.f;

        // write normalized P (tf32) — covers all 208 cols across both halves
#pragma unroll
        for (int ni = 0; ni < 13; ni++) {
            const int col = nb + ni*8 + 2*c;
            uint2 ulo = make_uint2(f2tf32(acc[ni][0]*rlo), f2tf32(acc[ni][1]*rlo));
            uint2 uhi = make_uint2(f2tf32(acc[ni][2]*rhi), f2tf32(acc[ni][3]*rhi));
            *(uint2*)&Pt[(mr+g)  *PP + col] = ulo;
            *(uint2*)&Pt[(mr+g+8)*PP + col] = uhi;
        }
        __syncthreads();

        // ---- O = P . V   (warp tile 16 x 40) ------------------------------
        const int nb2 = wn * 40;
        float o[5][4];
#pragma unroll
        for (int ni = 0; ni < 5; ni++)
#pragma unroll
            for (int r = 0; r < 4; r++) o[ni][r] = 0.f;

        const int kcap   = (thi < T_-1) ? thi : (T_-1);
        const int ks_end = kcap >> 3;              // inclusive 8-block index
        for (int ksb = 0; ksb <= ks_end; ksb++) {
            const int ks = ksb * 8;
            const uint32_t a0 = Pt[(mr+g)  *PP + ks+c];
            const uint32_t a1 = Pt[(mr+g+8)*PP + ks+c];
            const uint32_t a2 = Pt[(mr+g)  *PP + ks+c+4];
            const uint32_t a3 = Pt[(mr+g+8)*PP + ks+c+4];
#pragma unroll
            for (int ni = 0; ni < 5; ni++) {
                const uint32_t b0 = Vs[(ks+c)  *VP + nb2+ni*8+g];
                const uint32_t b1 = Vs[(ks+c+4)*VP + nb2+ni*8+g];
                mma_tf32(o[ni], a0, a1, a2, a3, b0, b1);
            }
        }

        // ---- epilogue: write g_att[(b*T+t)*E + h*HS + f] ------------------
#pragma unroll
        for (int ni = 0; ni < 5; ni++) {
#pragma unroll
            for (int r = 0; r < 4; r++) {
                const int t = t0 + mr + g + ((r >= 2) ? 8 : 0);
                const int f = nb2 + ni*8 + 2*c + (r & 1);
                if (t < T_ && f < HS_)
                    g_att[((size_t)(b*T_ + t))*E_ + h*HS_ + f] = o[ni][r];
            }
        }
    }
}

// ---------------------------------------------------------------------------
extern "C" void kernel_launch(void* const* d_in, const int* in_sizes, int n_in,
                              void* d_out, int out_size)
{
    const float* x  = (const float*)d_in[0];
    const float* Wq = (const float*)d_in[1];
    const float* Wk = (const float*)d_in[2];
    const float* Wv = (const float*)d_in[3];
    const float* Wo = (const float*)d_in[4];
    const float* bo = (const float*)d_in[5];
    float* out = (float*)d_out;

    const int att_smem = (TP2*KQ2 + TP2*VP + 64*QP + 64*PP + 256) * (int)sizeof(float);
    cudaFuncSetAttribute(attn_mma, cudaFuncAttributeMaxDynamicSharedMemorySize, att_smem);

    // QKV projection
    gemm_tf32<0><<<dim3(14, 400), 256>>>(x, Wq, Wk, Wv, nullptr, nullptr);

    // attention (tensor-core)
    attn_mma<<<BH_, 256, att_smem>>>();

    // output projection
    gemm_tf32<1><<<dim3(5, 400), 256>>>(nullptr, Wo, nullptr, nullptr, bo, out);
}